// round 14
// baseline (speedup 1.0000x reference)
#include <cuda_runtime.h>
#include <cuda_bf16.h>
#include <math.h>
#include <stdint.h>

#define BB 16
#define NN 4096
#define SS 1024
#define KK 32
#define M_ROWS (BB*SS*KK)        // 524288
#define OUT_XYZ_ELEMS (BB*SS*3)

#define RS1 40
#define STR 72    // bf16 row stride for mma smem tiles

// packed f32x2 helpers
#define ADD2(o,a,b) asm("add.rn.f32x2 %0,%1,%2;" : "=l"(o) : "l"(a), "l"(b))
#define MUL2(o,a,b) asm("mul.rn.f32x2 %0,%1,%2;" : "=l"(o) : "l"(a), "l"(b))
#define PACK2(o,lo,hi) asm("mov.b64 %0,{%1,%2};" : "=l"(o) : "f"(lo), "f"(hi))
#define UNPACK2(lo,hi,v) asm("mov.b64 {%0,%1},%2;" : "=f"(lo), "=f"(hi) : "l"(v))
#define REDUX_MAX(o,v) asm("redux.sync.max.s32 %0,%1,0xffffffff;" : "=r"(o) : "r"(v))
#define REDUX_MIN(o,v) asm("redux.sync.min.s32 %0,%1,0xffffffff;" : "=r"(o) : "r"(v))
#define PACKBF(o, hi, lo) asm("cvt.rn.bf16x2.f32 %0, %1, %2;" : "=r"(o) : "f"(hi), "f"(lo))

__device__ __forceinline__ void mma_bf16(float* d, const uint32_t* a, const uint32_t* b) {
    asm volatile("mma.sync.aligned.m16n8k16.row.col.f32.bf16.bf16.f32 "
        "{%0,%1,%2,%3}, {%4,%5,%6,%7}, {%8,%9}, {%0,%1,%2,%3};"
        : "+f"(d[0]), "+f"(d[1]), "+f"(d[2]), "+f"(d[3])
        : "r"(a[0]), "r"(a[1]), "r"(a[2]), "r"(a[3]), "r"(b[0]), "r"(b[1]));
}

// ---------------- scratch ----------------------------------------------------
__device__ float  g_y1[M_ROWS*64];
__device__ float  g_y2[M_ROWS*64];
__device__ float  g_mx[BB*SS*128];
__device__ float  g_mn[BB*SS*128];
__device__ int    g_ball[M_ROWS];
__device__ double g_sum1[64],  g_sq1[64];
__device__ double g_sum2[64],  g_sq2[64];
__device__ double g_sum3[128], g_sq3[128];
__device__ float  g_a1[64], g_c1[64];
__device__ float  g_a2[64], g_c2[64];
__device__ float  g_a3[128], g_c3[128];

__global__ void k_init() {
    int t = threadIdx.x;
    if (t < 64)  { g_sum1[t]=0.0; g_sq1[t]=0.0; g_sum2[t]=0.0; g_sq2[t]=0.0; }
    if (t < 128) { g_sum3[t]=0.0; g_sq3[t]=0.0; }
}

// ---------------- FPS v2: 1024 threads, 4 pts/thread, atomic single reduce ---
// Bit-exact vs reference: uncontracted mul/add distances; global argmax with
// first-index tie-break via 64-bit key (dist_bits<<32)|(0xFFFFFFFF-idx) and
// smem atomicMax (positive-float bits are order-isomorphic; larger complement
// = smaller index). 3-slot buffer rotation keeps one barrier per iteration:
// in window it, reads hit slot (it-1)%3, atomics hit it%3, reset hits (it+1)%3.
__global__ __launch_bounds__(1024) void k_fps(const float* __restrict__ xyz,
                                              float* __restrict__ newxyz) {
    extern __shared__ float sm[];
    float* sxs = sm; float* sys = sm + NN; float* szs = sm + 2*NN;
    __shared__ unsigned long long s_best[3];
    const int b = blockIdx.x, tid = threadIdx.x;
    const float* base = xyz + (size_t)b*NN*3;
    float pxs[4], pys[4], pzs[4], dist[4];
#pragma unroll
    for (int k = 0; k < 4; k++) {
        const int i = tid + (k << 10);
        float x = base[3*i+0], y = base[3*i+1], z = base[3*i+2];
        pxs[k]=x; pys[k]=y; pzs[k]=z;
        sxs[i]=x; sys[i]=y; szs[i]=z;
        dist[k] = 1e10f;
    }
    unsigned long long px2[2], py2[2], pz2[2];
#pragma unroll
    for (int j = 0; j < 2; j++) {
        PACK2(px2[j], pxs[2*j], pxs[2*j+1]);
        PACK2(py2[j], pys[2*j], pys[2*j+1]);
        PACK2(pz2[j], pzs[2*j], pzs[2*j+1]);
    }
    if (tid < 3) s_best[tid] = 0ull;
    float* outc = newxyz + (size_t)b*SS*3;
    __syncthreads();
    float ccx = sxs[0], ccy = sys[0], ccz = szs[0];
    if (tid == 0) { outc[0]=ccx; outc[1]=ccy; outc[2]=ccz; }
    const int lane = tid & 31;
    int cur = 0;
    for (int it = 0; it < SS-1; it++) {
        const float ncx = -ccx, ncy = -ccy, ncz = -ccz;
        unsigned long long ncx2, ncy2, ncz2;
        PACK2(ncx2, ncx, ncx); PACK2(ncy2, ncy, ncy); PACK2(ncz2, ncz, ncz);
        float bv = -1.0f;
#pragma unroll
        for (int j = 0; j < 2; j++) {
            unsigned long long dx,dy,dz,qx,qy,qz,s2,d2;
            ADD2(dx, px2[j], ncx2);
            ADD2(dy, py2[j], ncy2);
            ADD2(dz, pz2[j], ncz2);
            MUL2(qx, dx, dx); MUL2(qy, dy, dy); MUL2(qz, dz, dz);
            ADD2(s2, qx, qy); ADD2(d2, s2, qz);
            float d0, d1; UNPACK2(d0, d1, d2);
            dist[2*j]   = fminf(dist[2*j],   d0);
            dist[2*j+1] = fminf(dist[2*j+1], d1);
            bv = fmaxf(bv, dist[2*j]); bv = fmaxf(bv, dist[2*j+1]);
        }
        int vmax; REDUX_MAX(vmax, __float_as_int(bv));
        int ti = 0x7fffffff;
        if (__float_as_int(bv) == vmax) {
#pragma unroll
            for (int k = 3; k >= 0; k--)
                if (dist[k] == bv) ti = tid + (k << 10);
        }
        int imin; REDUX_MIN(imin, ti);
        if (lane == 0) {
            unsigned long long key =
                ((unsigned long long)(unsigned)vmax << 32) |
                (unsigned)(0xFFFFFFFFu - (unsigned)imin);
            atomicMax(&s_best[cur], key);
        }
        int nxt = cur + 1; if (nxt == 3) nxt = 0;
        if (tid == 0) s_best[nxt] = 0ull;   // reset slot (it+1)%3 — untouched this window
        __syncthreads();
        unsigned long long kb = s_best[cur];
        int idx = (int)(0xFFFFFFFFu - (unsigned)(kb & 0xFFFFFFFFull));
        ccx = sxs[idx]; ccy = sys[idx]; ccz = szs[idx];
        if (tid == 0) {
            outc[3*(it+1)+0]=ccx; outc[3*(it+1)+1]=ccy; outc[3*(it+1)+2]=ccz;
        }
        cur = nxt;
    }
}

// ---------------- ball query -------------------------------------------------
__global__ __launch_bounds__(1024) void k_ball(const float* __restrict__ xyz,
                                               const float* __restrict__ newxyz) {
    extern __shared__ float sm[];
    float* sx = sm; float* sy = sm + NN; float* sz = sm + 2*NN;
    const int b = blockIdx.y;
    const float* base = xyz + (size_t)b*NN*3;
    for (int i = threadIdx.x; i < NN; i += 1024) {
        sx[i] = base[3*i+0]; sy[i] = base[3*i+1]; sz[i] = base[3*i+2];
    }
    __syncthreads();
    const int wid = threadIdx.x >> 5, lane = threadIdx.x & 31;
    const int s = blockIdx.x * 32 + wid;
    const int g = b * SS + s;
    const float cx = newxyz[3*g+0], cy = newxyz[3*g+1], cz = newxyz[3*g+2];
    int* out = g_ball + (size_t)g*KK;
    int count = 0, first = -1;
    for (int j0 = 0; j0 < NN && count < KK; j0 += 32) {
        const int j = j0 + lane;
        float dx = sx[j]-cx, dy = sy[j]-cy, dz = sz[j]-cz;
        float d = __fadd_rn(__fadd_rn(__fmul_rn(dx,dx), __fmul_rn(dy,dy)),
                            __fmul_rn(dz,dz));
        const bool in = !(d > 0.04f);
        unsigned m = __ballot_sync(0xffffffffu, in);
        if (first < 0 && m) first = j0 + __ffs(m) - 1;
        int pre = __popc(m & ((1u << lane) - 1u));
        if (in) { int p = count + pre; if (p < KK) out[p] = j; }
        count += __popc(m);
    }
    if (count < KK) {
        for (int t = count + lane; t < KK; t += 32) out[t] = first;
    }
}

#define FMA4(W4, xs, j) \
    acc[0][j] = fmaf((W4).x, (xs), acc[0][j]); \
    acc[1][j] = fmaf((W4).y, (xs), acc[1][j]); \
    acc[2][j] = fmaf((W4).z, (xs), acc[2][j]); \
    acc[3][j] = fmaf((W4).w, (xs), acc[3][j]);

// ---------------- layer 1 (scalar, unchanged) --------------------------------
__global__ __launch_bounds__(256, 4) void k_layer1(const float* __restrict__ xyz,
                                                   const float* __restrict__ points,
                                                   const float* __restrict__ newxyz,
                                                   const float* __restrict__ w,
                                                   const float* __restrict__ bias) {
    __shared__ __align__(16) float sX[64*RS1];
    __shared__ __align__(16) float sWT[36*64];
    __shared__ __align__(16) float sred[16][64];
    __shared__ float sb[64];
    const int tid = threadIdx.x;
    if (tid < 64) sb[tid] = bias[tid];
    for (int e = tid; e < 36*64; e += 256) {
        int i = e >> 6, o = e & 63;
        float v = (i < 32) ? w[o*35 + 3 + i] : ((i < 35) ? w[o*35 + (i-32)] : 0.f);
        sWT[i*64 + o] = v;
    }
    __syncthreads();
    const int tx = tid & 15, ty = tid >> 4;
    const float bb0 = sb[4*tx+0], bb1 = sb[4*tx+1], bb2 = sb[4*tx+2], bb3 = sb[4*tx+3];
    float ls[4] = {0,0,0,0}, lq[4] = {0,0,0,0};
    for (int t = 0; t < 8; t++) {
        const int row0 = (blockIdx.x*8 + t) * 64;
        const int b = row0 >> 15;
        const int grp0 = row0 >> 5;
        __syncthreads();
        {
            const int r = tid >> 2, h = tid & 3;
            const int pidx = g_ball[row0 + r];
            const float4* prow = (const float4*)(points + ((size_t)b*NN + pidx)*32) + h*2;
            float4* dst = (float4*)(sX + r*RS1) + h*2;
            dst[0] = prow[0]; dst[1] = prow[1];
            if (h == 0) {
                const float* pc  = xyz + ((size_t)b*NN + pidx)*3;
                const float* cen = newxyz + (size_t)(grp0 + (r >> 5))*3;
                float4 v;
                v.x = pc[0]-cen[0]; v.y = pc[1]-cen[1]; v.z = pc[2]-cen[2]; v.w = 0.f;
                *(float4*)(sX + r*RS1 + 32) = v;
            }
        }
        __syncthreads();
        float acc[4][4];
#pragma unroll
        for (int j = 0; j < 4; j++) { acc[0][j]=bb0; acc[1][j]=bb1; acc[2][j]=bb2; acc[3][j]=bb3; }
#pragma unroll
        for (int i4 = 0; i4 < 9; i4++) {
            float4 w4[4];
#pragma unroll
            for (int ii = 0; ii < 4; ii++)
                w4[ii] = *(const float4*)(sWT + (i4*4+ii)*64 + 4*tx);
#pragma unroll
            for (int j = 0; j < 4; j++) {
                const float4 x4 = *(const float4*)(sX + (ty+16*j)*RS1 + i4*4);
                FMA4(w4[0], x4.x, j); FMA4(w4[1], x4.y, j);
                FMA4(w4[2], x4.z, j); FMA4(w4[3], x4.w, j);
            }
        }
#pragma unroll
        for (int j = 0; j < 4; j++) {
            float4 v;
            v.x = acc[0][j]; v.y = acc[1][j]; v.z = acc[2][j]; v.w = acc[3][j];
            *(float4*)(g_y1 + (size_t)(row0 + ty + 16*j)*64 + 4*tx) = v;
#pragma unroll
            for (int c = 0; c < 4; c++) { float y = acc[c][j]; ls[c] += y; lq[c] += y*y; }
        }
    }
    __syncthreads();
    *(float4*)&sred[ty][4*tx] = make_float4(ls[0], ls[1], ls[2], ls[3]);
    __syncthreads();
    if (tid < 64) {
        float t = 0.f;
#pragma unroll
        for (int yy = 0; yy < 16; yy++) t += sred[yy][tid];
        atomicAdd(&g_sum1[tid], (double)t);
    }
    __syncthreads();
    *(float4*)&sred[ty][4*tx] = make_float4(lq[0], lq[1], lq[2], lq[3]);
    __syncthreads();
    if (tid < 64) {
        float t = 0.f;
#pragma unroll
        for (int yy = 0; yy < 16; yy++) t += sred[yy][tid];
        atomicAdd(&g_sq1[tid], (double)t);
    }
}

// ---------------- split helpers ----------------------------------------------
__device__ __forceinline__ void split8(const float* x, uint4& H, uint4& L) {
    uint32_t h01,h23,h45,h67;
    PACKBF(h01, x[1], x[0]); PACKBF(h23, x[3], x[2]);
    PACKBF(h45, x[5], x[4]); PACKBF(h67, x[7], x[6]);
    float r[8];
    r[0] = x[0] - __uint_as_float(h01 << 16);
    r[1] = x[1] - __uint_as_float(h01 & 0xffff0000u);
    r[2] = x[2] - __uint_as_float(h23 << 16);
    r[3] = x[3] - __uint_as_float(h23 & 0xffff0000u);
    r[4] = x[4] - __uint_as_float(h45 << 16);
    r[5] = x[5] - __uint_as_float(h45 & 0xffff0000u);
    r[6] = x[6] - __uint_as_float(h67 << 16);
    r[7] = x[7] - __uint_as_float(h67 & 0xffff0000u);
    uint32_t l01,l23,l45,l67;
    PACKBF(l01, r[1], r[0]); PACKBF(l23, r[3], r[2]);
    PACKBF(l45, r[5], r[4]); PACKBF(l67, r[7], r[6]);
    H.x=h01; H.y=h23; H.z=h45; H.w=h67;
    L.x=l01; L.y=l23; L.z=l45; L.w=l67;
}

__device__ __forceinline__ void bnrelu8(const float4 a4, const float4 b4,
                                        const float* sa, const float* sc,
                                        int k8, float* x) {
    float4 A0 = *(const float4*)(sa + 8*k8);
    float4 C0 = *(const float4*)(sc + 8*k8);
    float4 A1 = *(const float4*)(sa + 8*k8 + 4);
    float4 C1 = *(const float4*)(sc + 8*k8 + 4);
    x[0] = fmaxf(fmaf(A0.x, a4.x, C0.x), 0.f);
    x[1] = fmaxf(fmaf(A0.y, a4.y, C0.y), 0.f);
    x[2] = fmaxf(fmaf(A0.z, a4.z, C0.z), 0.f);
    x[3] = fmaxf(fmaf(A0.w, a4.w, C0.w), 0.f);
    x[4] = fmaxf(fmaf(A1.x, b4.x, C1.x), 0.f);
    x[5] = fmaxf(fmaf(A1.y, b4.y, C1.y), 0.f);
    x[6] = fmaxf(fmaf(A1.z, b4.z, C1.z), 0.f);
    x[7] = fmaxf(fmaf(A1.w, b4.w, C1.w), 0.f);
}

// ---------------- layer 2: mma, 256 threads (R12 version) --------------------
__global__ __launch_bounds__(256, 2) void k_layer2m(const float* __restrict__ w,
                                                    const float* __restrict__ bias) {
    extern __shared__ __align__(16) __nv_bfloat16 dsm2[];
    __nv_bfloat16* Ah = dsm2;
    __nv_bfloat16* Al = Ah + 128*STR;
    __nv_bfloat16* Bh = Al + 128*STR;
    __nv_bfloat16* Bl = Bh + 64*STR;
    __shared__ float sa[64], sc[64], sb[64];
    __shared__ float s_sum[64], s_sq[64];
    const int tid = threadIdx.x, wid = tid >> 5, lane = tid & 31;
    const int g = lane >> 2, tg = lane & 3;
    const int rw = wid >> 1, cw = wid & 1;
    const int wr0 = rw * 32;
    if (tid < 64) { sa[tid]=g_a1[tid]; sc[tid]=g_c1[tid]; sb[tid]=bias[tid];
                    s_sum[tid]=0.f; s_sq[tid]=0.f; }
    for (int e = tid; e < 4096; e += 256) {
        int n = e >> 6, k = e & 63;
        float v = w[e];
        __nv_bfloat16 h = __float2bfloat16_rn(v);
        __nv_bfloat16 l = __float2bfloat16_rn(v - __bfloat162float(h));
        Bh[n*STR + k] = h; Bl[n*STR + k] = l;
    }
    float ls0[4]={0,0,0,0}, ls1[4]={0,0,0,0};
    float lq0[4]={0,0,0,0}, lq1[4]={0,0,0,0};
    for (int t = 0; t < 4; t++) {
        const int row0 = (blockIdx.x*4 + t) * 128;
        __syncthreads();
        {   // prologue: 2 threads per row
            const int r = tid >> 1, h = tid & 1;
            const float4* yr = (const float4*)(g_y1 + (size_t)(row0 + r)*64);
#pragma unroll
            for (int k8 = 0; k8 < 4; k8++) {
                const int kk = h*4 + k8;
                float x[8]; uint4 H, L;
                bnrelu8(yr[2*kk], yr[2*kk+1], sa, sc, kk, x);
                split8(x, H, L);
                *(uint4*)(Ah + r*STR + kk*8) = H;
                *(uint4*)(Al + r*STR + kk*8) = L;
            }
        }
        __syncthreads();
        float d[2][4][4];
#pragma unroll
        for (int mt = 0; mt < 2; mt++)
#pragma unroll
            for (int nt = 0; nt < 4; nt++)
#pragma unroll
                for (int q = 0; q < 4; q++) d[mt][nt][q] = 0.f;
#pragma unroll
        for (int pass = 0; pass < 3; pass++) {
            const __nv_bfloat16* Ab = (pass == 2) ? Al : Ah;
            const __nv_bfloat16* Bb = (pass == 1) ? Bl : Bh;
#pragma unroll
            for (int ks = 0; ks < 4; ks++) {
                uint32_t a[2][4];
#pragma unroll
                for (int mt = 0; mt < 2; mt++) {
                    const __nv_bfloat16* ap = Ab + (wr0 + mt*16)*STR + ks*16;
                    a[mt][0] = *(const uint32_t*)(ap + g*STR + 2*tg);
                    a[mt][1] = *(const uint32_t*)(ap + (g+8)*STR + 2*tg);
                    a[mt][2] = *(const uint32_t*)(ap + g*STR + 2*tg + 8);
                    a[mt][3] = *(const uint32_t*)(ap + (g+8)*STR + 2*tg + 8);
                }
#pragma unroll
                for (int nt = 0; nt < 4; nt++) {
                    uint32_t b[2];
                    const __nv_bfloat16* bp = Bb + (cw*32 + nt*8 + g)*STR + ks*16 + 2*tg;
                    b[0] = *(const uint32_t*)(bp);
                    b[1] = *(const uint32_t*)(bp + 8);
                    mma_bf16(d[0][nt], a[0], b);
                    mma_bf16(d[1][nt], a[1], b);
                }
            }
        }
#pragma unroll
        for (int nt = 0; nt < 4; nt++) {
            const int ch0 = cw*32 + nt*8 + 2*tg;
            const float bv0 = sb[ch0], bv1 = sb[ch0 + 1];
#pragma unroll
            for (int mt = 0; mt < 2; mt++) {
                float v0 = d[mt][nt][0] + bv0, v1 = d[mt][nt][1] + bv1;
                float v2 = d[mt][nt][2] + bv0, v3 = d[mt][nt][3] + bv1;
                const size_t r = (size_t)(row0 + wr0 + mt*16 + g);
                *(float2*)(g_y2 + r*64 + ch0)     = make_float2(v0, v1);
                *(float2*)(g_y2 + (r+8)*64 + ch0) = make_float2(v2, v3);
                ls0[nt] += v0 + v2; ls1[nt] += v1 + v3;
                lq0[nt] += v0*v0 + v2*v2; lq1[nt] += v1*v1 + v3*v3;
            }
        }
    }
#pragma unroll
    for (int nt = 0; nt < 4; nt++) {
        float s0 = ls0[nt], s1 = ls1[nt], q0 = lq0[nt], q1 = lq1[nt];
#pragma unroll
        for (int off = 16; off >= 4; off >>= 1) {
            s0 += __shfl_down_sync(0xffffffffu, s0, off);
            s1 += __shfl_down_sync(0xffffffffu, s1, off);
            q0 += __shfl_down_sync(0xffffffffu, q0, off);
            q1 += __shfl_down_sync(0xffffffffu, q1, off);
        }
        if (g == 0) {
            const int ch0 = cw*32 + nt*8 + 2*tg;
            atomicAdd(&s_sum[ch0],     s0);
            atomicAdd(&s_sum[ch0 + 1], s1);
            atomicAdd(&s_sq [ch0],     q0);
            atomicAdd(&s_sq [ch0 + 1], q1);
        }
    }
    __syncthreads();
    if (tid < 64) {
        atomicAdd(&g_sum2[tid], (double)s_sum[tid]);
        atomicAdd(&g_sq2[tid],  (double)s_sq[tid]);
    }
}

// ---------------- layer 3: mma, 256 threads (R12 version) --------------------
__global__ __launch_bounds__(256, 2) void k_layer3m(const float* __restrict__ w,
                                                    const float* __restrict__ bias) {
    extern __shared__ __align__(16) __nv_bfloat16 dsm3[];
    __nv_bfloat16* Ah = dsm3;
    __nv_bfloat16* Al = Ah + 128*STR;
    __nv_bfloat16* Bh = Al + 128*STR;
    __nv_bfloat16* Bl = Bh + 128*STR;
    __shared__ float sa[64], sc[64], sb[128];
    __shared__ float s_sum[128], s_sq[128];
    const int tid = threadIdx.x, wid = tid >> 5, lane = tid & 31;
    const int g = lane >> 2, tg = lane & 3;
    const int rw = wid >> 1, cw = wid & 1;
    const int wr0 = rw * 32;
    if (tid < 64)  { sa[tid]=g_a2[tid]; sc[tid]=g_c2[tid]; }
    if (tid < 128) { sb[tid]=bias[tid]; s_sum[tid]=0.f; s_sq[tid]=0.f; }
    for (int e = tid; e < 8192; e += 256) {
        int n = e >> 6, k = e & 63;
        float v = w[e];
        __nv_bfloat16 h = __float2bfloat16_rn(v);
        __nv_bfloat16 l = __float2bfloat16_rn(v - __bfloat162float(h));
        Bh[n*STR + k] = h; Bl[n*STR + k] = l;
    }
    float ls0[2][4]={{0,0,0,0},{0,0,0,0}}, ls1[2][4]={{0,0,0,0},{0,0,0,0}};
    float lq0[2][4]={{0,0,0,0},{0,0,0,0}}, lq1[2][4]={{0,0,0,0},{0,0,0,0}};
    for (int t = 0; t < 4; t++) {
        const int row0 = (blockIdx.x*4 + t) * 128;
        const int grp = (row0 >> 5) + rw;
        __syncthreads();
        {   // prologue: 2 threads per row
            const int r = tid >> 1, h = tid & 1;
            const float4* yr = (const float4*)(g_y2 + (size_t)(row0 + r)*64);
#pragma unroll
            for (int k8 = 0; k8 < 4; k8++) {
                const int kk = h*4 + k8;
                float x[8]; uint4 H, L;
                bnrelu8(yr[2*kk], yr[2*kk+1], sa, sc, kk, x);
                split8(x, H, L);
                *(uint4*)(Ah + r*STR + kk*8) = H;
                *(uint4*)(Al + r*STR + kk*8) = L;
            }
        }
        __syncthreads();
#pragma unroll
        for (int nh = 0; nh < 2; nh++) {
            float d[2][4][4];
#pragma unroll
            for (int mt = 0; mt < 2; mt++)
#pragma unroll
                for (int nt = 0; nt < 4; nt++)
#pragma unroll
                    for (int q = 0; q < 4; q++) d[mt][nt][q] = 0.f;
#pragma unroll
            for (int pass = 0; pass < 3; pass++) {
                const __nv_bfloat16* Ab = (pass == 2) ? Al : Ah;
                const __nv_bfloat16* Bb = (pass == 1) ? Bl : Bh;
#pragma unroll
                for (int ks = 0; ks < 4; ks++) {
                    uint32_t a[2][4];
#pragma unroll
                    for (int mt = 0; mt < 2; mt++) {
                        const __nv_bfloat16* ap = Ab + (wr0 + mt*16)*STR + ks*16;
                        a[mt][0] = *(const uint32_t*)(ap + g*STR + 2*tg);
                        a[mt][1] = *(const uint32_t*)(ap + (g+8)*STR + 2*tg);
                        a[mt][2] = *(const uint32_t*)(ap + g*STR + 2*tg + 8);
                        a[mt][3] = *(const uint32_t*)(ap + (g+8)*STR + 2*tg + 8);
                    }
#pragma unroll
                    for (int nt = 0; nt < 4; nt++) {
                        uint32_t b[2];
                        const __nv_bfloat16* bp = Bb + (nh*64 + cw*32 + nt*8 + g)*STR + ks*16 + 2*tg;
                        b[0] = *(const uint32_t*)(bp);
                        b[1] = *(const uint32_t*)(bp + 8);
                        mma_bf16(d[0][nt], a[0], b);
                        mma_bf16(d[1][nt], a[1], b);
                    }
                }
            }
#pragma unroll
            for (int nt = 0; nt < 4; nt++) {
                const int ch0 = nh*64 + cw*32 + nt*8 + 2*tg;
                const float bv0 = sb[ch0], bv1 = sb[ch0 + 1];
                float v00 = d[0][nt][0]+bv0, v01 = d[0][nt][1]+bv1;
                float v02 = d[0][nt][2]+bv0, v03 = d[0][nt][3]+bv1;
                float v10 = d[1][nt][0]+bv0, v11 = d[1][nt][1]+bv1;
                float v12 = d[1][nt][2]+bv0, v13 = d[1][nt][3]+bv1;
                ls0[nh][nt] += v00+v02+v10+v12;
                ls1[nh][nt] += v01+v03+v11+v13;
                lq0[nh][nt] += v00*v00+v02*v02+v10*v10+v12*v12;
                lq1[nh][nt] += v01*v01+v03*v03+v11*v11+v13*v13;
                float mx0 = fmaxf(fmaxf(v00,v02), fmaxf(v10,v12));
                float mx1 = fmaxf(fmaxf(v01,v03), fmaxf(v11,v13));
                float mn0 = fminf(fminf(v00,v02), fminf(v10,v12));
                float mn1 = fminf(fminf(v01,v03), fminf(v11,v13));
#pragma unroll
                for (int off = 16; off >= 4; off >>= 1) {
                    mx0 = fmaxf(mx0, __shfl_down_sync(0xffffffffu, mx0, off));
                    mx1 = fmaxf(mx1, __shfl_down_sync(0xffffffffu, mx1, off));
                    mn0 = fminf(mn0, __shfl_down_sync(0xffffffffu, mn0, off));
                    mn1 = fminf(mn1, __shfl_down_sync(0xffffffffu, mn1, off));
                }
                if (g == 0) {
                    g_mx[(size_t)grp*128 + ch0]     = mx0;
                    g_mx[(size_t)grp*128 + ch0 + 1] = mx1;
                    g_mn[(size_t)grp*128 + ch0]     = mn0;
                    g_mn[(size_t)grp*128 + ch0 + 1] = mn1;
                }
            }
        }
    }
#pragma unroll
    for (int nh = 0; nh < 2; nh++)
#pragma unroll
    for (int nt = 0; nt < 4; nt++) {
        float s0 = ls0[nh][nt], s1 = ls1[nh][nt];
        float q0 = lq0[nh][nt], q1 = lq1[nh][nt];
#pragma unroll
        for (int off = 16; off >= 4; off >>= 1) {
            s0 += __shfl_down_sync(0xffffffffu, s0, off);
            s1 += __shfl_down_sync(0xffffffffu, s1, off);
            q0 += __shfl_down_sync(0xffffffffu, q0, off);
            q1 += __shfl_down_sync(0xffffffffu, q1, off);
        }
        if (g == 0) {
            const int ch0 = nh*64 + cw*32 + nt*8 + 2*tg;
            atomicAdd(&s_sum[ch0],     s0);
            atomicAdd(&s_sum[ch0 + 1], s1);
            atomicAdd(&s_sq [ch0],     q0);
            atomicAdd(&s_sq [ch0 + 1], q1);
        }
    }
    __syncthreads();
    if (tid < 128) {
        atomicAdd(&g_sum3[tid], (double)s_sum[tid]);
        atomicAdd(&g_sq3[tid],  (double)s_sq[tid]);
    }
}

// ---------------- BN parameter derivation ------------------------------------
__global__ void k_bn(int layer, const float* __restrict__ gg,
                     const float* __restrict__ be, int n) {
    int i = threadIdx.x;
    if (i >= n) return;
    const double* sum; const double* sq; float* a; float* c;
    if (layer == 0)      { sum = g_sum1; sq = g_sq1; a = g_a1; c = g_c1; }
    else if (layer == 1) { sum = g_sum2; sq = g_sq2; a = g_a2; c = g_c2; }
    else                 { sum = g_sum3; sq = g_sq3; a = g_a3; c = g_c3; }
    const double invM = 1.0 / (double)M_ROWS;
    double mean = sum[i] * invM;
    double var  = sq[i] * invM - mean * mean;
    double A = (double)gg[i] / sqrt(var + 1e-5);
    a[i] = (float)A;
    c[i] = (float)((double)be[i] - A * mean);
}

// ---------------- final ------------------------------------------------------
__global__ __launch_bounds__(256) void k_final(float* __restrict__ out) {
    int gid = blockIdx.x * 256 + threadIdx.x;
    int s  = gid & 1023;
    int ch = (gid >> 10) & 127;
    int b  = gid >> 17;
    float A = g_a3[ch], C = g_c3[ch];
    size_t gi = ((size_t)((b << 10) | s))*128 + ch;
    float m = (A >= 0.f) ? g_mx[gi] : g_mn[gi];
    out[OUT_XYZ_ELEMS + gid] = fmaxf(fmaf(A, m, C), 0.f);
}

// ---------------- launch -----------------------------------------------------
extern "C" void kernel_launch(void* const* d_in, const int* in_sizes, int n_in,
                              void* d_out, int out_size) {
    const float* xyz    = (const float*)d_in[0];
    const float* points = (const float*)d_in[1];
    const float* w0  = (const float*)d_in[2];
    const float* b0  = (const float*)d_in[3];
    const float* g0  = (const float*)d_in[4];
    const float* be0 = (const float*)d_in[5];
    const float* w1  = (const float*)d_in[6];
    const float* b1  = (const float*)d_in[7];
    const float* g1  = (const float*)d_in[8];
    const float* be1 = (const float*)d_in[9];
    const float* w2  = (const float*)d_in[10];
    const float* b2  = (const float*)d_in[11];
    const float* g2  = (const float*)d_in[12];
    const float* be2 = (const float*)d_in[13];
    float* out = (float*)d_out;
    (void)in_sizes; (void)n_in; (void)out_size;

    const size_t smem_xyz  = (size_t)3 * NN * sizeof(float);      // 48KB
    const size_t smem_l2   = (size_t)(2*128*STR + 2*64*STR) * 2;  // 55296B
    const size_t smem_l3   = (size_t)(2*128*STR + 2*128*STR) * 2; // 73728B
    static int attr_done = 0;
    if (!attr_done) {
        cudaFuncSetAttribute(k_fps,  cudaFuncAttributeMaxDynamicSharedMemorySize, (int)smem_xyz);
        cudaFuncSetAttribute(k_ball, cudaFuncAttributeMaxDynamicSharedMemorySize, (int)smem_xyz);
        cudaFuncSetAttribute(k_layer2m, cudaFuncAttributeMaxDynamicSharedMemorySize, (int)smem_l2);
        cudaFuncSetAttribute(k_layer3m, cudaFuncAttributeMaxDynamicSharedMemorySize, (int)smem_l3);
        attr_done = 1;
    }

    // k_fps is the 4th launch (profiler captures launch #4) — keep measuring it.
    k_init<<<1, 128>>>();
    k_init<<<1, 128>>>();
    k_init<<<1, 128>>>();
    k_fps<<<BB, 1024, smem_xyz>>>(xyz, out);
    k_ball<<<dim3(SS/32, BB), 1024, smem_xyz>>>(xyz, out);
    k_layer1<<<1024, 256>>>(xyz, points, out, w0, b0);
    k_bn<<<1, 128>>>(0, g0, be0, 64);
    k_layer2m<<<1024, 256, smem_l2>>>(w1, b1);
    k_bn<<<1, 128>>>(1, g1, be1, 64);
    k_layer3m<<<1024, 256, smem_l3>>>(w2, b2);
    k_bn<<<1, 128>>>(2, g2, be2, 128);
    k_final<<<(BB*128*SS)/256, 256>>>(out);
}

// round 15
// speedup vs baseline: 1.0167x; 1.0167x over previous
#include <cuda_runtime.h>
#include <cuda_bf16.h>
#include <math.h>
#include <stdint.h>

#define BB 16
#define NN 4096
#define SS 1024
#define KK 32
#define M_ROWS (BB*SS*KK)        // 524288
#define OUT_XYZ_ELEMS (BB*SS*3)

#define RS1 40
#define STR 72    // bf16 row stride for mma smem tiles

// packed f32x2 helpers
#define ADD2(o,a,b) asm("add.rn.f32x2 %0,%1,%2;" : "=l"(o) : "l"(a), "l"(b))
#define MUL2(o,a,b) asm("mul.rn.f32x2 %0,%1,%2;" : "=l"(o) : "l"(a), "l"(b))
#define PACK2(o,lo,hi) asm("mov.b64 %0,{%1,%2};" : "=l"(o) : "f"(lo), "f"(hi))
#define UNPACK2(lo,hi,v) asm("mov.b64 {%0,%1},%2;" : "=f"(lo), "=f"(hi) : "l"(v))
#define REDUX_MAX(o,v) asm("redux.sync.max.s32 %0,%1,0xffffffff;" : "=r"(o) : "r"(v))
#define REDUX_MIN(o,v) asm("redux.sync.min.s32 %0,%1,0xffffffff;" : "=r"(o) : "r"(v))
#define PACKBF(o, hi, lo) asm("cvt.rn.bf16x2.f32 %0, %1, %2;" : "=r"(o) : "f"(hi), "f"(lo))

__device__ __forceinline__ void mma_bf16(float* d, const uint32_t* a, const uint32_t* b) {
    asm volatile("mma.sync.aligned.m16n8k16.row.col.f32.bf16.bf16.f32 "
        "{%0,%1,%2,%3}, {%4,%5,%6,%7}, {%8,%9}, {%0,%1,%2,%3};"
        : "+f"(d[0]), "+f"(d[1]), "+f"(d[2]), "+f"(d[3])
        : "r"(a[0]), "r"(a[1]), "r"(a[2]), "r"(a[3]), "r"(b[0]), "r"(b[1]));
}

// ---------------- scratch ----------------------------------------------------
__device__ float  g_y1[M_ROWS*64];
__device__ float  g_y2[M_ROWS*64];
__device__ float  g_mx[BB*SS*128];
__device__ float  g_mn[BB*SS*128];
__device__ int    g_ball[M_ROWS];
__device__ double g_sum1[64],  g_sq1[64];
__device__ double g_sum2[64],  g_sq2[64];
__device__ double g_sum3[128], g_sq3[128];
__device__ float  g_a1[64], g_c1[64];
__device__ float  g_a2[64], g_c2[64];
__device__ float  g_a3[128], g_c3[128];

__global__ void k_init() {
    int t = threadIdx.x;
    if (t < 64)  { g_sum1[t]=0.0; g_sq1[t]=0.0; g_sum2[t]=0.0; g_sq2[t]=0.0; }
    if (t < 128) { g_sum3[t]=0.0; g_sq3[t]=0.0; }
}

// ---------------- FPS (R12 version — measured 389us, frozen) -----------------
__global__ __launch_bounds__(512) void k_fps(const float* __restrict__ xyz,
                                             float* __restrict__ newxyz) {
    extern __shared__ float sm[];
    float* sxs = sm; float* sys = sm + NN; float* szs = sm + 2*NN;
    __shared__ float swv[2][16];
    __shared__ int   swi[2][16];
    const int b = blockIdx.x, tid = threadIdx.x;
    const float* base = xyz + (size_t)b*NN*3;
    float pxs[8], pys[8], pzs[8], dist[8];
#pragma unroll
    for (int k = 0; k < 8; k++) {
        const int i = tid + (k << 9);
        float x = base[3*i+0], y = base[3*i+1], z = base[3*i+2];
        pxs[k]=x; pys[k]=y; pzs[k]=z;
        sxs[i]=x; sys[i]=y; szs[i]=z;
        dist[k] = 1e10f;
    }
    unsigned long long px2[4], py2[4], pz2[4];
#pragma unroll
    for (int j = 0; j < 4; j++) {
        PACK2(px2[j], pxs[2*j], pxs[2*j+1]);
        PACK2(py2[j], pys[2*j], pys[2*j+1]);
        PACK2(pz2[j], pzs[2*j], pzs[2*j+1]);
    }
    float* outc = newxyz + (size_t)b*SS*3;
    __syncthreads();
    float ccx = sxs[0], ccy = sys[0], ccz = szs[0];
    if (tid == 0) { outc[0]=ccx; outc[1]=ccy; outc[2]=ccz; }
    const int lane = tid & 31, w = tid >> 5;
    for (int it = 0; it < SS-1; it++) {
        const int pb = it & 1;
        const float ncx = -ccx, ncy = -ccy, ncz = -ccz;
        unsigned long long ncx2, ncy2, ncz2;
        PACK2(ncx2, ncx, ncx); PACK2(ncy2, ncy, ncy); PACK2(ncz2, ncz, ncz);
        float bv = -1.0f;
#pragma unroll
        for (int j = 0; j < 4; j++) {
            unsigned long long dx,dy,dz,qx,qy,qz,s2,d2;
            ADD2(dx, px2[j], ncx2);
            ADD2(dy, py2[j], ncy2);
            ADD2(dz, pz2[j], ncz2);
            MUL2(qx, dx, dx); MUL2(qy, dy, dy); MUL2(qz, dz, dz);
            ADD2(s2, qx, qy); ADD2(d2, s2, qz);
            float d0, d1; UNPACK2(d0, d1, d2);
            dist[2*j]   = fminf(dist[2*j],   d0);
            dist[2*j+1] = fminf(dist[2*j+1], d1);
            bv = fmaxf(bv, dist[2*j]); bv = fmaxf(bv, dist[2*j+1]);
        }
        int vmax; REDUX_MAX(vmax, __float_as_int(bv));
        int ti = 0x7fffffff;
        if (__float_as_int(bv) == vmax) {
#pragma unroll
            for (int k = 7; k >= 0; k--)
                if (dist[k] == bv) ti = tid + (k << 9);
        }
        int imin; REDUX_MIN(imin, ti);
        if (lane == 0) { swv[pb][w] = __int_as_float(vmax); swi[pb][w] = imin; }
        __syncthreads();
        float v  = (lane < 16) ? swv[pb][lane] : -1.0f;
        int   i2 = (lane < 16) ? swi[pb][lane] : 0x7fffffff;
        int vg; REDUX_MAX(vg, __float_as_int(v));
        int t2 = (__float_as_int(v) == vg) ? i2 : 0x7fffffff;
        int ig; REDUX_MIN(ig, t2);
        ccx = sxs[ig]; ccy = sys[ig]; ccz = szs[ig];
        if (tid == 0) {
            outc[3*(it+1)+0]=ccx; outc[3*(it+1)+1]=ccy; outc[3*(it+1)+2]=ccz;
        }
    }
}

// ---------------- ball query -------------------------------------------------
__global__ __launch_bounds__(1024) void k_ball(const float* __restrict__ xyz,
                                               const float* __restrict__ newxyz) {
    extern __shared__ float sm[];
    float* sx = sm; float* sy = sm + NN; float* sz = sm + 2*NN;
    const int b = blockIdx.y;
    const float* base = xyz + (size_t)b*NN*3;
    for (int i = threadIdx.x; i < NN; i += 1024) {
        sx[i] = base[3*i+0]; sy[i] = base[3*i+1]; sz[i] = base[3*i+2];
    }
    __syncthreads();
    const int wid = threadIdx.x >> 5, lane = threadIdx.x & 31;
    const int s = blockIdx.x * 32 + wid;
    const int g = b * SS + s;
    const float cx = newxyz[3*g+0], cy = newxyz[3*g+1], cz = newxyz[3*g+2];
    int* out = g_ball + (size_t)g*KK;
    int count = 0, first = -1;
    for (int j0 = 0; j0 < NN && count < KK; j0 += 32) {
        const int j = j0 + lane;
        float dx = sx[j]-cx, dy = sy[j]-cy, dz = sz[j]-cz;
        float d = __fadd_rn(__fadd_rn(__fmul_rn(dx,dx), __fmul_rn(dy,dy)),
                            __fmul_rn(dz,dz));
        const bool in = !(d > 0.04f);
        unsigned m = __ballot_sync(0xffffffffu, in);
        if (first < 0 && m) first = j0 + __ffs(m) - 1;
        int pre = __popc(m & ((1u << lane) - 1u));
        if (in) { int p = count + pre; if (p < KK) out[p] = j; }
        count += __popc(m);
    }
    if (count < KK) {
        for (int t = count + lane; t < KK; t += 32) out[t] = first;
    }
}

#define FMA4(W4, xs, j) \
    acc[0][j] = fmaf((W4).x, (xs), acc[0][j]); \
    acc[1][j] = fmaf((W4).y, (xs), acc[1][j]); \
    acc[2][j] = fmaf((W4).z, (xs), acc[2][j]); \
    acc[3][j] = fmaf((W4).w, (xs), acc[3][j]);

// ---------------- layer 1 (scalar, unchanged) --------------------------------
__global__ __launch_bounds__(256, 4) void k_layer1(const float* __restrict__ xyz,
                                                   const float* __restrict__ points,
                                                   const float* __restrict__ newxyz,
                                                   const float* __restrict__ w,
                                                   const float* __restrict__ bias) {
    __shared__ __align__(16) float sX[64*RS1];
    __shared__ __align__(16) float sWT[36*64];
    __shared__ __align__(16) float sred[16][64];
    __shared__ float sb[64];
    const int tid = threadIdx.x;
    if (tid < 64) sb[tid] = bias[tid];
    for (int e = tid; e < 36*64; e += 256) {
        int i = e >> 6, o = e & 63;
        float v = (i < 32) ? w[o*35 + 3 + i] : ((i < 35) ? w[o*35 + (i-32)] : 0.f);
        sWT[i*64 + o] = v;
    }
    __syncthreads();
    const int tx = tid & 15, ty = tid >> 4;
    const float bb0 = sb[4*tx+0], bb1 = sb[4*tx+1], bb2 = sb[4*tx+2], bb3 = sb[4*tx+3];
    float ls[4] = {0,0,0,0}, lq[4] = {0,0,0,0};
    for (int t = 0; t < 8; t++) {
        const int row0 = (blockIdx.x*8 + t) * 64;
        const int b = row0 >> 15;
        const int grp0 = row0 >> 5;
        __syncthreads();
        {
            const int r = tid >> 2, h = tid & 3;
            const int pidx = g_ball[row0 + r];
            const float4* prow = (const float4*)(points + ((size_t)b*NN + pidx)*32) + h*2;
            float4* dst = (float4*)(sX + r*RS1) + h*2;
            dst[0] = prow[0]; dst[1] = prow[1];
            if (h == 0) {
                const float* pc  = xyz + ((size_t)b*NN + pidx)*3;
                const float* cen = newxyz + (size_t)(grp0 + (r >> 5))*3;
                float4 v;
                v.x = pc[0]-cen[0]; v.y = pc[1]-cen[1]; v.z = pc[2]-cen[2]; v.w = 0.f;
                *(float4*)(sX + r*RS1 + 32) = v;
            }
        }
        __syncthreads();
        float acc[4][4];
#pragma unroll
        for (int j = 0; j < 4; j++) { acc[0][j]=bb0; acc[1][j]=bb1; acc[2][j]=bb2; acc[3][j]=bb3; }
#pragma unroll
        for (int i4 = 0; i4 < 9; i4++) {
            float4 w4[4];
#pragma unroll
            for (int ii = 0; ii < 4; ii++)
                w4[ii] = *(const float4*)(sWT + (i4*4+ii)*64 + 4*tx);
#pragma unroll
            for (int j = 0; j < 4; j++) {
                const float4 x4 = *(const float4*)(sX + (ty+16*j)*RS1 + i4*4);
                FMA4(w4[0], x4.x, j); FMA4(w4[1], x4.y, j);
                FMA4(w4[2], x4.z, j); FMA4(w4[3], x4.w, j);
            }
        }
#pragma unroll
        for (int j = 0; j < 4; j++) {
            float4 v;
            v.x = acc[0][j]; v.y = acc[1][j]; v.z = acc[2][j]; v.w = acc[3][j];
            *(float4*)(g_y1 + (size_t)(row0 + ty + 16*j)*64 + 4*tx) = v;
#pragma unroll
            for (int c = 0; c < 4; c++) { float y = acc[c][j]; ls[c] += y; lq[c] += y*y; }
        }
    }
    __syncthreads();
    *(float4*)&sred[ty][4*tx] = make_float4(ls[0], ls[1], ls[2], ls[3]);
    __syncthreads();
    if (tid < 64) {
        float t = 0.f;
#pragma unroll
        for (int yy = 0; yy < 16; yy++) t += sred[yy][tid];
        atomicAdd(&g_sum1[tid], (double)t);
    }
    __syncthreads();
    *(float4*)&sred[ty][4*tx] = make_float4(lq[0], lq[1], lq[2], lq[3]);
    __syncthreads();
    if (tid < 64) {
        float t = 0.f;
#pragma unroll
        for (int yy = 0; yy < 16; yy++) t += sred[yy][tid];
        atomicAdd(&g_sq1[tid], (double)t);
    }
}

// ---------------- split helpers ----------------------------------------------
__device__ __forceinline__ void split8(const float* x, uint4& H, uint4& L) {
    uint32_t h01,h23,h45,h67;
    PACKBF(h01, x[1], x[0]); PACKBF(h23, x[3], x[2]);
    PACKBF(h45, x[5], x[4]); PACKBF(h67, x[7], x[6]);
    float r[8];
    r[0] = x[0] - __uint_as_float(h01 << 16);
    r[1] = x[1] - __uint_as_float(h01 & 0xffff0000u);
    r[2] = x[2] - __uint_as_float(h23 << 16);
    r[3] = x[3] - __uint_as_float(h23 & 0xffff0000u);
    r[4] = x[4] - __uint_as_float(h45 << 16);
    r[5] = x[5] - __uint_as_float(h45 & 0xffff0000u);
    r[6] = x[6] - __uint_as_float(h67 << 16);
    r[7] = x[7] - __uint_as_float(h67 & 0xffff0000u);
    uint32_t l01,l23,l45,l67;
    PACKBF(l01, r[1], r[0]); PACKBF(l23, r[3], r[2]);
    PACKBF(l45, r[5], r[4]); PACKBF(l67, r[7], r[6]);
    H.x=h01; H.y=h23; H.z=h45; H.w=h67;
    L.x=l01; L.y=l23; L.z=l45; L.w=l67;
}

__device__ __forceinline__ void bnrelu8(const float4 a4, const float4 b4,
                                        const float* sa, const float* sc,
                                        int k8, float* x) {
    float4 A0 = *(const float4*)(sa + 8*k8);
    float4 C0 = *(const float4*)(sc + 8*k8);
    float4 A1 = *(const float4*)(sa + 8*k8 + 4);
    float4 C1 = *(const float4*)(sc + 8*k8 + 4);
    x[0] = fmaxf(fmaf(A0.x, a4.x, C0.x), 0.f);
    x[1] = fmaxf(fmaf(A0.y, a4.y, C0.y), 0.f);
    x[2] = fmaxf(fmaf(A0.z, a4.z, C0.z), 0.f);
    x[3] = fmaxf(fmaf(A0.w, a4.w, C0.w), 0.f);
    x[4] = fmaxf(fmaf(A1.x, b4.x, C1.x), 0.f);
    x[5] = fmaxf(fmaf(A1.y, b4.y, C1.y), 0.f);
    x[6] = fmaxf(fmaf(A1.z, b4.z, C1.z), 0.f);
    x[7] = fmaxf(fmaf(A1.w, b4.w, C1.w), 0.f);
}

// ---------------- layer 2: mma, 256 threads, 3 blocks/SM ---------------------
__global__ __launch_bounds__(256, 3) void k_layer2m(const float* __restrict__ w,
                                                    const float* __restrict__ bias) {
    extern __shared__ __align__(16) __nv_bfloat16 dsm2[];
    __nv_bfloat16* Ah = dsm2;
    __nv_bfloat16* Al = Ah + 128*STR;
    __nv_bfloat16* Bh = Al + 128*STR;
    __nv_bfloat16* Bl = Bh + 64*STR;
    __shared__ float sa[64], sc[64], sb[64];
    __shared__ float s_sum[64], s_sq[64];
    const int tid = threadIdx.x, wid = tid >> 5, lane = tid & 31;
    const int g = lane >> 2, tg = lane & 3;
    const int rw = wid >> 1, cw = wid & 1;
    const int wr0 = rw * 32;
    if (tid < 64) { sa[tid]=g_a1[tid]; sc[tid]=g_c1[tid]; sb[tid]=bias[tid];
                    s_sum[tid]=0.f; s_sq[tid]=0.f; }
    for (int e = tid; e < 4096; e += 256) {
        int n = e >> 6, k = e & 63;
        float v = w[e];
        __nv_bfloat16 h = __float2bfloat16_rn(v);
        __nv_bfloat16 l = __float2bfloat16_rn(v - __bfloat162float(h));
        Bh[n*STR + k] = h; Bl[n*STR + k] = l;
    }
    float ls0[4]={0,0,0,0}, ls1[4]={0,0,0,0};
    float lq0[4]={0,0,0,0}, lq1[4]={0,0,0,0};
    for (int t = 0; t < 4; t++) {
        const int row0 = (blockIdx.x*4 + t) * 128;
        __syncthreads();
        {   // prologue: 2 threads per row
            const int r = tid >> 1, h = tid & 1;
            const float4* yr = (const float4*)(g_y1 + (size_t)(row0 + r)*64);
#pragma unroll
            for (int k8 = 0; k8 < 4; k8++) {
                const int kk = h*4 + k8;
                float x[8]; uint4 H, L;
                bnrelu8(yr[2*kk], yr[2*kk+1], sa, sc, kk, x);
                split8(x, H, L);
                *(uint4*)(Ah + r*STR + kk*8) = H;
                *(uint4*)(Al + r*STR + kk*8) = L;
            }
        }
        __syncthreads();
        float d[2][4][4];
#pragma unroll
        for (int mt = 0; mt < 2; mt++)
#pragma unroll
            for (int nt = 0; nt < 4; nt++)
#pragma unroll
                for (int q = 0; q < 4; q++) d[mt][nt][q] = 0.f;
#pragma unroll
        for (int pass = 0; pass < 3; pass++) {
            const __nv_bfloat16* Ab = (pass == 2) ? Al : Ah;
            const __nv_bfloat16* Bb = (pass == 1) ? Bl : Bh;
#pragma unroll
            for (int ks = 0; ks < 4; ks++) {
                uint32_t a[2][4];
#pragma unroll
                for (int mt = 0; mt < 2; mt++) {
                    const __nv_bfloat16* ap = Ab + (wr0 + mt*16)*STR + ks*16;
                    a[mt][0] = *(const uint32_t*)(ap + g*STR + 2*tg);
                    a[mt][1] = *(const uint32_t*)(ap + (g+8)*STR + 2*tg);
                    a[mt][2] = *(const uint32_t*)(ap + g*STR + 2*tg + 8);
                    a[mt][3] = *(const uint32_t*)(ap + (g+8)*STR + 2*tg + 8);
                }
#pragma unroll
                for (int nt = 0; nt < 4; nt++) {
                    uint32_t b[2];
                    const __nv_bfloat16* bp = Bb + (cw*32 + nt*8 + g)*STR + ks*16 + 2*tg;
                    b[0] = *(const uint32_t*)(bp);
                    b[1] = *(const uint32_t*)(bp + 8);
                    mma_bf16(d[0][nt], a[0], b);
                    mma_bf16(d[1][nt], a[1], b);
                }
            }
        }
#pragma unroll
        for (int nt = 0; nt < 4; nt++) {
            const int ch0 = cw*32 + nt*8 + 2*tg;
            const float bv0 = sb[ch0], bv1 = sb[ch0 + 1];
#pragma unroll
            for (int mt = 0; mt < 2; mt++) {
                float v0 = d[mt][nt][0] + bv0, v1 = d[mt][nt][1] + bv1;
                float v2 = d[mt][nt][2] + bv0, v3 = d[mt][nt][3] + bv1;
                const size_t r = (size_t)(row0 + wr0 + mt*16 + g);
                *(float2*)(g_y2 + r*64 + ch0)     = make_float2(v0, v1);
                *(float2*)(g_y2 + (r+8)*64 + ch0) = make_float2(v2, v3);
                ls0[nt] += v0 + v2; ls1[nt] += v1 + v3;
                lq0[nt] += v0*v0 + v2*v2; lq1[nt] += v1*v1 + v3*v3;
            }
        }
    }
#pragma unroll
    for (int nt = 0; nt < 4; nt++) {
        float s0 = ls0[nt], s1 = ls1[nt], q0 = lq0[nt], q1 = lq1[nt];
#pragma unroll
        for (int off = 16; off >= 4; off >>= 1) {
            s0 += __shfl_down_sync(0xffffffffu, s0, off);
            s1 += __shfl_down_sync(0xffffffffu, s1, off);
            q0 += __shfl_down_sync(0xffffffffu, q0, off);
            q1 += __shfl_down_sync(0xffffffffu, q1, off);
        }
        if (g == 0) {
            const int ch0 = cw*32 + nt*8 + 2*tg;
            atomicAdd(&s_sum[ch0],     s0);
            atomicAdd(&s_sum[ch0 + 1], s1);
            atomicAdd(&s_sq [ch0],     q0);
            atomicAdd(&s_sq [ch0 + 1], q1);
        }
    }
    __syncthreads();
    if (tid < 64) {
        atomicAdd(&g_sum2[tid], (double)s_sum[tid]);
        atomicAdd(&g_sq2[tid],  (double)s_sq[tid]);
    }
}

// ---------------- layer 3: mma, 256 threads, 3 blocks/SM ---------------------
__global__ __launch_bounds__(256, 3) void k_layer3m(const float* __restrict__ w,
                                                    const float* __restrict__ bias) {
    extern __shared__ __align__(16) __nv_bfloat16 dsm3[];
    __nv_bfloat16* Ah = dsm3;
    __nv_bfloat16* Al = Ah + 128*STR;
    __nv_bfloat16* Bh = Al + 128*STR;
    __nv_bfloat16* Bl = Bh + 128*STR;
    __shared__ float sa[64], sc[64], sb[128];
    __shared__ float s_sum[128], s_sq[128];
    const int tid = threadIdx.x, wid = tid >> 5, lane = tid & 31;
    const int g = lane >> 2, tg = lane & 3;
    const int rw = wid >> 1, cw = wid & 1;
    const int wr0 = rw * 32;
    if (tid < 64)  { sa[tid]=g_a2[tid]; sc[tid]=g_c2[tid]; }
    if (tid < 128) { sb[tid]=bias[tid]; s_sum[tid]=0.f; s_sq[tid]=0.f; }
    for (int e = tid; e < 8192; e += 256) {
        int n = e >> 6, k = e & 63;
        float v = w[e];
        __nv_bfloat16 h = __float2bfloat16_rn(v);
        __nv_bfloat16 l = __float2bfloat16_rn(v - __bfloat162float(h));
        Bh[n*STR + k] = h; Bl[n*STR + k] = l;
    }
    float ls0[2][4]={{0,0,0,0},{0,0,0,0}}, ls1[2][4]={{0,0,0,0},{0,0,0,0}};
    float lq0[2][4]={{0,0,0,0},{0,0,0,0}}, lq1[2][4]={{0,0,0,0},{0,0,0,0}};
    for (int t = 0; t < 4; t++) {
        const int row0 = (blockIdx.x*4 + t) * 128;
        const int grp = (row0 >> 5) + rw;
        __syncthreads();
        {   // prologue: 2 threads per row
            const int r = tid >> 1, h = tid & 1;
            const float4* yr = (const float4*)(g_y2 + (size_t)(row0 + r)*64);
#pragma unroll
            for (int k8 = 0; k8 < 4; k8++) {
                const int kk = h*4 + k8;
                float x[8]; uint4 H, L;
                bnrelu8(yr[2*kk], yr[2*kk+1], sa, sc, kk, x);
                split8(x, H, L);
                *(uint4*)(Ah + r*STR + kk*8) = H;
                *(uint4*)(Al + r*STR + kk*8) = L;
            }
        }
        __syncthreads();
#pragma unroll
        for (int nh = 0; nh < 2; nh++) {
            float d[2][4][4];
#pragma unroll
            for (int mt = 0; mt < 2; mt++)
#pragma unroll
                for (int nt = 0; nt < 4; nt++)
#pragma unroll
                    for (int q = 0; q < 4; q++) d[mt][nt][q] = 0.f;
#pragma unroll
            for (int pass = 0; pass < 3; pass++) {
                const __nv_bfloat16* Ab = (pass == 2) ? Al : Ah;
                const __nv_bfloat16* Bb = (pass == 1) ? Bl : Bh;
#pragma unroll
                for (int ks = 0; ks < 4; ks++) {
                    uint32_t a[2][4];
#pragma unroll
                    for (int mt = 0; mt < 2; mt++) {
                        const __nv_bfloat16* ap = Ab + (wr0 + mt*16)*STR + ks*16;
                        a[mt][0] = *(const uint32_t*)(ap + g*STR + 2*tg);
                        a[mt][1] = *(const uint32_t*)(ap + (g+8)*STR + 2*tg);
                        a[mt][2] = *(const uint32_t*)(ap + g*STR + 2*tg + 8);
                        a[mt][3] = *(const uint32_t*)(ap + (g+8)*STR + 2*tg + 8);
                    }
#pragma unroll
                    for (int nt = 0; nt < 4; nt++) {
                        uint32_t b[2];
                        const __nv_bfloat16* bp = Bb + (nh*64 + cw*32 + nt*8 + g)*STR + ks*16 + 2*tg;
                        b[0] = *(const uint32_t*)(bp);
                        b[1] = *(const uint32_t*)(bp + 8);
                        mma_bf16(d[0][nt], a[0], b);
                        mma_bf16(d[1][nt], a[1], b);
                    }
                }
            }
#pragma unroll
            for (int nt = 0; nt < 4; nt++) {
                const int ch0 = nh*64 + cw*32 + nt*8 + 2*tg;
                const float bv0 = sb[ch0], bv1 = sb[ch0 + 1];
                float v00 = d[0][nt][0]+bv0, v01 = d[0][nt][1]+bv1;
                float v02 = d[0][nt][2]+bv0, v03 = d[0][nt][3]+bv1;
                float v10 = d[1][nt][0]+bv0, v11 = d[1][nt][1]+bv1;
                float v12 = d[1][nt][2]+bv0, v13 = d[1][nt][3]+bv1;
                ls0[nh][nt] += v00+v02+v10+v12;
                ls1[nh][nt] += v01+v03+v11+v13;
                lq0[nh][nt] += v00*v00+v02*v02+v10*v10+v12*v12;
                lq1[nh][nt] += v01*v01+v03*v03+v11*v11+v13*v13;
                float mx0 = fmaxf(fmaxf(v00,v02), fmaxf(v10,v12));
                float mx1 = fmaxf(fmaxf(v01,v03), fmaxf(v11,v13));
                float mn0 = fminf(fminf(v00,v02), fminf(v10,v12));
                float mn1 = fminf(fminf(v01,v03), fminf(v11,v13));
#pragma unroll
                for (int off = 16; off >= 4; off >>= 1) {
                    mx0 = fmaxf(mx0, __shfl_down_sync(0xffffffffu, mx0, off));
                    mx1 = fmaxf(mx1, __shfl_down_sync(0xffffffffu, mx1, off));
                    mn0 = fminf(mn0, __shfl_down_sync(0xffffffffu, mn0, off));
                    mn1 = fminf(mn1, __shfl_down_sync(0xffffffffu, mn1, off));
                }
                if (g == 0) {
                    g_mx[(size_t)grp*128 + ch0]     = mx0;
                    g_mx[(size_t)grp*128 + ch0 + 1] = mx1;
                    g_mn[(size_t)grp*128 + ch0]     = mn0;
                    g_mn[(size_t)grp*128 + ch0 + 1] = mn1;
                }
            }
        }
    }
#pragma unroll
    for (int nh = 0; nh < 2; nh++)
#pragma unroll
    for (int nt = 0; nt < 4; nt++) {
        float s0 = ls0[nh][nt], s1 = ls1[nh][nt];
        float q0 = lq0[nh][nt], q1 = lq1[nh][nt];
#pragma unroll
        for (int off = 16; off >= 4; off >>= 1) {
            s0 += __shfl_down_sync(0xffffffffu, s0, off);
            s1 += __shfl_down_sync(0xffffffffu, s1, off);
            q0 += __shfl_down_sync(0xffffffffu, q0, off);
            q1 += __shfl_down_sync(0xffffffffu, q1, off);
        }
        if (g == 0) {
            const int ch0 = nh*64 + cw*32 + nt*8 + 2*tg;
            atomicAdd(&s_sum[ch0],     s0);
            atomicAdd(&s_sum[ch0 + 1], s1);
            atomicAdd(&s_sq [ch0],     q0);
            atomicAdd(&s_sq [ch0 + 1], q1);
        }
    }
    __syncthreads();
    if (tid < 128) {
        atomicAdd(&g_sum3[tid], (double)s_sum[tid]);
        atomicAdd(&g_sq3[tid],  (double)s_sq[tid]);
    }
}

// ---------------- BN parameter derivation ------------------------------------
__global__ void k_bn(int layer, const float* __restrict__ gg,
                     const float* __restrict__ be, int n) {
    int i = threadIdx.x;
    if (i >= n) return;
    const double* sum; const double* sq; float* a; float* c;
    if (layer == 0)      { sum = g_sum1; sq = g_sq1; a = g_a1; c = g_c1; }
    else if (layer == 1) { sum = g_sum2; sq = g_sq2; a = g_a2; c = g_c2; }
    else                 { sum = g_sum3; sq = g_sq3; a = g_a3; c = g_c3; }
    const double invM = 1.0 / (double)M_ROWS;
    double mean = sum[i] * invM;
    double var  = sq[i] * invM - mean * mean;
    double A = (double)gg[i] / sqrt(var + 1e-5);
    a[i] = (float)A;
    c[i] = (float)((double)be[i] - A * mean);
}

// ---------------- final ------------------------------------------------------
__global__ __launch_bounds__(256) void k_final(float* __restrict__ out) {
    int gid = blockIdx.x * 256 + threadIdx.x;
    int s  = gid & 1023;
    int ch = (gid >> 10) & 127;
    int b  = gid >> 17;
    float A = g_a3[ch], C = g_c3[ch];
    size_t gi = ((size_t)((b << 10) | s))*128 + ch;
    float m = (A >= 0.f) ? g_mx[gi] : g_mn[gi];
    out[OUT_XYZ_ELEMS + gid] = fmaxf(fmaf(A, m, C), 0.f);
}

// ---------------- launch -----------------------------------------------------
extern "C" void kernel_launch(void* const* d_in, const int* in_sizes, int n_in,
                              void* d_out, int out_size) {
    const float* xyz    = (const float*)d_in[0];
    const float* points = (const float*)d_in[1];
    const float* w0  = (const float*)d_in[2];
    const float* b0  = (const float*)d_in[3];
    const float* g0  = (const float*)d_in[4];
    const float* be0 = (const float*)d_in[5];
    const float* w1  = (const float*)d_in[6];
    const float* b1  = (const float*)d_in[7];
    const float* g1  = (const float*)d_in[8];
    const float* be1 = (const float*)d_in[9];
    const float* w2  = (const float*)d_in[10];
    const float* b2  = (const float*)d_in[11];
    const float* g2  = (const float*)d_in[12];
    const float* be2 = (const float*)d_in[13];
    float* out = (float*)d_out;
    (void)in_sizes; (void)n_in; (void)out_size;

    const size_t smem_xyz  = (size_t)3 * NN * sizeof(float);      // 48KB
    const size_t smem_l2   = (size_t)(2*128*STR + 2*64*STR) * 2;  // 55296B
    const size_t smem_l3   = (size_t)(2*128*STR + 2*128*STR) * 2; // 73728B
    static int attr_done = 0;
    if (!attr_done) {
        cudaFuncSetAttribute(k_fps,  cudaFuncAttributeMaxDynamicSharedMemorySize, (int)smem_xyz);
        cudaFuncSetAttribute(k_ball, cudaFuncAttributeMaxDynamicSharedMemorySize, (int)smem_xyz);
        cudaFuncSetAttribute(k_layer2m, cudaFuncAttributeMaxDynamicSharedMemorySize, (int)smem_l2);
        cudaFuncSetAttribute(k_layer3m, cudaFuncAttributeMaxDynamicSharedMemorySize, (int)smem_l3);
        attr_done = 1;
    }

    // k_layer2m in profile slot #4 this round (3 inits + fps... adjust: keep
    // fps measured config but place layer2m 4th by removing padding).
    k_init<<<1, 128>>>();
    k_fps<<<BB, 512, smem_xyz>>>(xyz, out);
    k_ball<<<dim3(SS/32, BB), 1024, smem_xyz>>>(xyz, out);
    k_layer2m_probe:;
    k_layer1<<<1024, 256>>>(xyz, points, out, w0, b0);
    k_bn<<<1, 128>>>(0, g0, be0, 64);
    k_layer2m<<<1024, 256, smem_l2>>>(w1, b1);
    k_bn<<<1, 128>>>(1, g1, be1, 64);
    k_layer3m<<<1024, 256, smem_l3>>>(w2, b2);
    k_bn<<<1, 128>>>(2, g2, be2, 128);
    k_final<<<(BB*128*SS)/256, 256>>>(out);
}

// round 16
// speedup vs baseline: 1.1910x; 1.1714x over previous
#include <cuda_runtime.h>
#include <cuda_bf16.h>
#include <math.h>
#include <stdint.h>

#define BB 16
#define NN 4096
#define SS 1024
#define KK 32
#define M_ROWS (BB*SS*KK)        // 524288
#define OUT_XYZ_ELEMS (BB*SS*3)

#define RS1 40
#define STR 72    // bf16 row stride for mma smem tiles

// packed f32x2 helpers
#define ADD2(o,a,b) asm("add.rn.f32x2 %0,%1,%2;" : "=l"(o) : "l"(a), "l"(b))
#define MUL2(o,a,b) asm("mul.rn.f32x2 %0,%1,%2;" : "=l"(o) : "l"(a), "l"(b))
#define PACK2(o,lo,hi) asm("mov.b64 %0,{%1,%2};" : "=l"(o) : "f"(lo), "f"(hi))
#define UNPACK2(lo,hi,v) asm("mov.b64 {%0,%1},%2;" : "=f"(lo), "=f"(hi) : "l"(v))
#define REDUX_MAX(o,v) asm("redux.sync.max.s32 %0,%1,0xffffffff;" : "=r"(o) : "r"(v))
#define REDUX_MIN(o,v) asm("redux.sync.min.s32 %0,%1,0xffffffff;" : "=r"(o) : "r"(v))
#define PACKBF(o, hi, lo) asm("cvt.rn.bf16x2.f32 %0, %1, %2;" : "=r"(o) : "f"(hi), "f"(lo))

__device__ __forceinline__ void mma_bf16(float* d, const uint32_t* a, const uint32_t* b) {
    asm volatile("mma.sync.aligned.m16n8k16.row.col.f32.bf16.bf16.f32 "
        "{%0,%1,%2,%3}, {%4,%5,%6,%7}, {%8,%9}, {%0,%1,%2,%3};"
        : "+f"(d[0]), "+f"(d[1]), "+f"(d[2]), "+f"(d[3])
        : "r"(a[0]), "r"(a[1]), "r"(a[2]), "r"(a[3]), "r"(b[0]), "r"(b[1]));
}

// ---------------- scratch ----------------------------------------------------
__device__ float  g_y1[M_ROWS*64];
__device__ float  g_y2[M_ROWS*64];
__device__ float  g_mx[BB*SS*128];
__device__ float  g_mn[BB*SS*128];
__device__ int    g_ball[M_ROWS];
__device__ double g_sum1[64],  g_sq1[64];
__device__ double g_sum2[64],  g_sq2[64];
__device__ double g_sum3[128], g_sq3[128];
__device__ float  g_a1[64], g_c1[64];
__device__ float  g_a2[64], g_c2[64];
__device__ float  g_a3[128], g_c3[128];

__global__ void k_init() {
    int t = threadIdx.x;
    if (t < 64)  { g_sum1[t]=0.0; g_sq1[t]=0.0; g_sum2[t]=0.0; g_sq2[t]=0.0; }
    if (t < 128) { g_sum3[t]=0.0; g_sq3[t]=0.0; }
}

// ---------------- FPS (R12 version — measured 389us, frozen) -----------------
__global__ __launch_bounds__(512) void k_fps(const float* __restrict__ xyz,
                                             float* __restrict__ newxyz) {
    extern __shared__ float sm[];
    float* sxs = sm; float* sys = sm + NN; float* szs = sm + 2*NN;
    __shared__ float swv[2][16];
    __shared__ int   swi[2][16];
    const int b = blockIdx.x, tid = threadIdx.x;
    const float* base = xyz + (size_t)b*NN*3;
    float pxs[8], pys[8], pzs[8], dist[8];
#pragma unroll
    for (int k = 0; k < 8; k++) {
        const int i = tid + (k << 9);
        float x = base[3*i+0], y = base[3*i+1], z = base[3*i+2];
        pxs[k]=x; pys[k]=y; pzs[k]=z;
        sxs[i]=x; sys[i]=y; szs[i]=z;
        dist[k] = 1e10f;
    }
    unsigned long long px2[4], py2[4], pz2[4];
#pragma unroll
    for (int j = 0; j < 4; j++) {
        PACK2(px2[j], pxs[2*j], pxs[2*j+1]);
        PACK2(py2[j], pys[2*j], pys[2*j+1]);
        PACK2(pz2[j], pzs[2*j], pzs[2*j+1]);
    }
    float* outc = newxyz + (size_t)b*SS*3;
    __syncthreads();
    float ccx = sxs[0], ccy = sys[0], ccz = szs[0];
    if (tid == 0) { outc[0]=ccx; outc[1]=ccy; outc[2]=ccz; }
    const int lane = tid & 31, w = tid >> 5;
    for (int it = 0; it < SS-1; it++) {
        const int pb = it & 1;
        const float ncx = -ccx, ncy = -ccy, ncz = -ccz;
        unsigned long long ncx2, ncy2, ncz2;
        PACK2(ncx2, ncx, ncx); PACK2(ncy2, ncy, ncy); PACK2(ncz2, ncz, ncz);
        float bv = -1.0f;
#pragma unroll
        for (int j = 0; j < 4; j++) {
            unsigned long long dx,dy,dz,qx,qy,qz,s2,d2;
            ADD2(dx, px2[j], ncx2);
            ADD2(dy, py2[j], ncy2);
            ADD2(dz, pz2[j], ncz2);
            MUL2(qx, dx, dx); MUL2(qy, dy, dy); MUL2(qz, dz, dz);
            ADD2(s2, qx, qy); ADD2(d2, s2, qz);
            float d0, d1; UNPACK2(d0, d1, d2);
            dist[2*j]   = fminf(dist[2*j],   d0);
            dist[2*j+1] = fminf(dist[2*j+1], d1);
            bv = fmaxf(bv, dist[2*j]); bv = fmaxf(bv, dist[2*j+1]);
        }
        int vmax; REDUX_MAX(vmax, __float_as_int(bv));
        int ti = 0x7fffffff;
        if (__float_as_int(bv) == vmax) {
#pragma unroll
            for (int k = 7; k >= 0; k--)
                if (dist[k] == bv) ti = tid + (k << 9);
        }
        int imin; REDUX_MIN(imin, ti);
        if (lane == 0) { swv[pb][w] = __int_as_float(vmax); swi[pb][w] = imin; }
        __syncthreads();
        float v  = (lane < 16) ? swv[pb][lane] : -1.0f;
        int   i2 = (lane < 16) ? swi[pb][lane] : 0x7fffffff;
        int vg; REDUX_MAX(vg, __float_as_int(v));
        int t2 = (__float_as_int(v) == vg) ? i2 : 0x7fffffff;
        int ig; REDUX_MIN(ig, t2);
        ccx = sxs[ig]; ccy = sys[ig]; ccz = szs[ig];
        if (tid == 0) {
            outc[3*(it+1)+0]=ccx; outc[3*(it+1)+1]=ccy; outc[3*(it+1)+2]=ccz;
        }
    }
}

// ---------------- ball query -------------------------------------------------
__global__ __launch_bounds__(1024) void k_ball(const float* __restrict__ xyz,
                                               const float* __restrict__ newxyz) {
    extern __shared__ float sm[];
    float* sx = sm; float* sy = sm + NN; float* sz = sm + 2*NN;
    const int b = blockIdx.y;
    const float* base = xyz + (size_t)b*NN*3;
    for (int i = threadIdx.x; i < NN; i += 1024) {
        sx[i] = base[3*i+0]; sy[i] = base[3*i+1]; sz[i] = base[3*i+2];
    }
    __syncthreads();
    const int wid = threadIdx.x >> 5, lane = threadIdx.x & 31;
    const int s = blockIdx.x * 32 + wid;
    const int g = b * SS + s;
    const float cx = newxyz[3*g+0], cy = newxyz[3*g+1], cz = newxyz[3*g+2];
    int* out = g_ball + (size_t)g*KK;
    int count = 0, first = -1;
    for (int j0 = 0; j0 < NN && count < KK; j0 += 32) {
        const int j = j0 + lane;
        float dx = sx[j]-cx, dy = sy[j]-cy, dz = sz[j]-cz;
        float d = __fadd_rn(__fadd_rn(__fmul_rn(dx,dx), __fmul_rn(dy,dy)),
                            __fmul_rn(dz,dz));
        const bool in = !(d > 0.04f);
        unsigned m = __ballot_sync(0xffffffffu, in);
        if (first < 0 && m) first = j0 + __ffs(m) - 1;
        int pre = __popc(m & ((1u << lane) - 1u));
        if (in) { int p = count + pre; if (p < KK) out[p] = j; }
        count += __popc(m);
    }
    if (count < KK) {
        for (int t = count + lane; t < KK; t += 32) out[t] = first;
    }
}

#define FMA4(W4, xs, j) \
    acc[0][j] = fmaf((W4).x, (xs), acc[0][j]); \
    acc[1][j] = fmaf((W4).y, (xs), acc[1][j]); \
    acc[2][j] = fmaf((W4).z, (xs), acc[2][j]); \
    acc[3][j] = fmaf((W4).w, (xs), acc[3][j]);

// ---------------- layer 1 (scalar) -------------------------------------------
__global__ __launch_bounds__(256, 4) void k_layer1(const float* __restrict__ xyz,
                                                   const float* __restrict__ points,
                                                   const float* __restrict__ newxyz,
                                                   const float* __restrict__ w,
                                                   const float* __restrict__ bias) {
    __shared__ __align__(16) float sX[64*RS1];
    __shared__ __align__(16) float sWT[36*64];
    __shared__ __align__(16) float sred[16][64];
    __shared__ float sb[64];
    const int tid = threadIdx.x;
    if (tid < 64) sb[tid] = bias[tid];
    for (int e = tid; e < 36*64; e += 256) {
        int i = e >> 6, o = e & 63;
        float v = (i < 32) ? w[o*35 + 3 + i] : ((i < 35) ? w[o*35 + (i-32)] : 0.f);
        sWT[i*64 + o] = v;
    }
    __syncthreads();
    const int tx = tid & 15, ty = tid >> 4;
    const float bb0 = sb[4*tx+0], bb1 = sb[4*tx+1], bb2 = sb[4*tx+2], bb3 = sb[4*tx+3];
    float ls[4] = {0,0,0,0}, lq[4] = {0,0,0,0};
    for (int t = 0; t < 8; t++) {
        const int row0 = (blockIdx.x*8 + t) * 64;
        const int b = row0 >> 15;
        const int grp0 = row0 >> 5;
        __syncthreads();
        {
            const int r = tid >> 2, h = tid & 3;
            const int pidx = g_ball[row0 + r];
            const float4* prow = (const float4*)(points + ((size_t)b*NN + pidx)*32) + h*2;
            float4* dst = (float4*)(sX + r*RS1) + h*2;
            dst[0] = prow[0]; dst[1] = prow[1];
            if (h == 0) {
                const float* pc  = xyz + ((size_t)b*NN + pidx)*3;
                const float* cen = newxyz + (size_t)(grp0 + (r >> 5))*3;
                float4 v;
                v.x = pc[0]-cen[0]; v.y = pc[1]-cen[1]; v.z = pc[2]-cen[2]; v.w = 0.f;
                *(float4*)(sX + r*RS1 + 32) = v;
            }
        }
        __syncthreads();
        float acc[4][4];
#pragma unroll
        for (int j = 0; j < 4; j++) { acc[0][j]=bb0; acc[1][j]=bb1; acc[2][j]=bb2; acc[3][j]=bb3; }
#pragma unroll
        for (int i4 = 0; i4 < 9; i4++) {
            float4 w4[4];
#pragma unroll
            for (int ii = 0; ii < 4; ii++)
                w4[ii] = *(const float4*)(sWT + (i4*4+ii)*64 + 4*tx);
#pragma unroll
            for (int j = 0; j < 4; j++) {
                const float4 x4 = *(const float4*)(sX + (ty+16*j)*RS1 + i4*4);
                FMA4(w4[0], x4.x, j); FMA4(w4[1], x4.y, j);
                FMA4(w4[2], x4.z, j); FMA4(w4[3], x4.w, j);
            }
        }
#pragma unroll
        for (int j = 0; j < 4; j++) {
            float4 v;
            v.x = acc[0][j]; v.y = acc[1][j]; v.z = acc[2][j]; v.w = acc[3][j];
            *(float4*)(g_y1 + (size_t)(row0 + ty + 16*j)*64 + 4*tx) = v;
#pragma unroll
            for (int c = 0; c < 4; c++) { float y = acc[c][j]; ls[c] += y; lq[c] += y*y; }
        }
    }
    __syncthreads();
    *(float4*)&sred[ty][4*tx] = make_float4(ls[0], ls[1], ls[2], ls[3]);
    __syncthreads();
    if (tid < 64) {
        float t = 0.f;
#pragma unroll
        for (int yy = 0; yy < 16; yy++) t += sred[yy][tid];
        atomicAdd(&g_sum1[tid], (double)t);
    }
    __syncthreads();
    *(float4*)&sred[ty][4*tx] = make_float4(lq[0], lq[1], lq[2], lq[3]);
    __syncthreads();
    if (tid < 64) {
        float t = 0.f;
#pragma unroll
        for (int yy = 0; yy < 16; yy++) t += sred[yy][tid];
        atomicAdd(&g_sq1[tid], (double)t);
    }
}

// ---------------- split helpers ----------------------------------------------
__device__ __forceinline__ void split8(const float* x, uint4& H, uint4& L) {
    uint32_t h01,h23,h45,h67;
    PACKBF(h01, x[1], x[0]); PACKBF(h23, x[3], x[2]);
    PACKBF(h45, x[5], x[4]); PACKBF(h67, x[7], x[6]);
    float r[8];
    r[0] = x[0] - __uint_as_float(h01 << 16);
    r[1] = x[1] - __uint_as_float(h01 & 0xffff0000u);
    r[2] = x[2] - __uint_as_float(h23 << 16);
    r[3] = x[3] - __uint_as_float(h23 & 0xffff0000u);
    r[4] = x[4] - __uint_as_float(h45 << 16);
    r[5] = x[5] - __uint_as_float(h45 & 0xffff0000u);
    r[6] = x[6] - __uint_as_float(h67 << 16);
    r[7] = x[7] - __uint_as_float(h67 & 0xffff0000u);
    uint32_t l01,l23,l45,l67;
    PACKBF(l01, r[1], r[0]); PACKBF(l23, r[3], r[2]);
    PACKBF(l45, r[5], r[4]); PACKBF(l67, r[7], r[6]);
    H.x=h01; H.y=h23; H.z=h45; H.w=h67;
    L.x=l01; L.y=l23; L.z=l45; L.w=l67;
}

__device__ __forceinline__ void bnrelu8(const float4 a4, const float4 b4,
                                        const float* sa, const float* sc,
                                        int k8, float* x) {
    float4 A0 = *(const float4*)(sa + 8*k8);
    float4 C0 = *(const float4*)(sc + 8*k8);
    float4 A1 = *(const float4*)(sa + 8*k8 + 4);
    float4 C1 = *(const float4*)(sc + 8*k8 + 4);
    x[0] = fmaxf(fmaf(A0.x, a4.x, C0.x), 0.f);
    x[1] = fmaxf(fmaf(A0.y, a4.y, C0.y), 0.f);
    x[2] = fmaxf(fmaf(A0.z, a4.z, C0.z), 0.f);
    x[3] = fmaxf(fmaf(A0.w, a4.w, C0.w), 0.f);
    x[4] = fmaxf(fmaf(A1.x, b4.x, C1.x), 0.f);
    x[5] = fmaxf(fmaf(A1.y, b4.y, C1.y), 0.f);
    x[6] = fmaxf(fmaf(A1.z, b4.z, C1.z), 0.f);
    x[7] = fmaxf(fmaf(A1.w, b4.w, C1.w), 0.f);
}

// ---------------- layer 2: mma, 256 threads, 2 blocks/SM (R12) ---------------
__global__ __launch_bounds__(256, 2) void k_layer2m(const float* __restrict__ w,
                                                    const float* __restrict__ bias) {
    extern __shared__ __align__(16) __nv_bfloat16 dsm2[];
    __nv_bfloat16* Ah = dsm2;
    __nv_bfloat16* Al = Ah + 128*STR;
    __nv_bfloat16* Bh = Al + 128*STR;
    __nv_bfloat16* Bl = Bh + 64*STR;
    __shared__ float sa[64], sc[64], sb[64];
    __shared__ float s_sum[64], s_sq[64];
    const int tid = threadIdx.x, wid = tid >> 5, lane = tid & 31;
    const int g = lane >> 2, tg = lane & 3;
    const int rw = wid >> 1, cw = wid & 1;
    const int wr0 = rw * 32;
    if (tid < 64) { sa[tid]=g_a1[tid]; sc[tid]=g_c1[tid]; sb[tid]=bias[tid];
                    s_sum[tid]=0.f; s_sq[tid]=0.f; }
    for (int e = tid; e < 4096; e += 256) {
        int n = e >> 6, k = e & 63;
        float v = w[e];
        __nv_bfloat16 h = __float2bfloat16_rn(v);
        __nv_bfloat16 l = __float2bfloat16_rn(v - __bfloat162float(h));
        Bh[n*STR + k] = h; Bl[n*STR + k] = l;
    }
    float ls0[4]={0,0,0,0}, ls1[4]={0,0,0,0};
    float lq0[4]={0,0,0,0}, lq1[4]={0,0,0,0};
    for (int t = 0; t < 4; t++) {
        const int row0 = (blockIdx.x*4 + t) * 128;
        __syncthreads();
        {   // prologue: 2 threads per row
            const int r = tid >> 1, h = tid & 1;
            const float4* yr = (const float4*)(g_y1 + (size_t)(row0 + r)*64);
#pragma unroll
            for (int k8 = 0; k8 < 4; k8++) {
                const int kk = h*4 + k8;
                float x[8]; uint4 H, L;
                bnrelu8(yr[2*kk], yr[2*kk+1], sa, sc, kk, x);
                split8(x, H, L);
                *(uint4*)(Ah + r*STR + kk*8) = H;
                *(uint4*)(Al + r*STR + kk*8) = L;
            }
        }
        __syncthreads();
        float d[2][4][4];
#pragma unroll
        for (int mt = 0; mt < 2; mt++)
#pragma unroll
            for (int nt = 0; nt < 4; nt++)
#pragma unroll
                for (int q = 0; q < 4; q++) d[mt][nt][q] = 0.f;
#pragma unroll
        for (int pass = 0; pass < 3; pass++) {
            const __nv_bfloat16* Ab = (pass == 2) ? Al : Ah;
            const __nv_bfloat16* Bb = (pass == 1) ? Bl : Bh;
#pragma unroll
            for (int ks = 0; ks < 4; ks++) {
                uint32_t a[2][4];
#pragma unroll
                for (int mt = 0; mt < 2; mt++) {
                    const __nv_bfloat16* ap = Ab + (wr0 + mt*16)*STR + ks*16;
                    a[mt][0] = *(const uint32_t*)(ap + g*STR + 2*tg);
                    a[mt][1] = *(const uint32_t*)(ap + (g+8)*STR + 2*tg);
                    a[mt][2] = *(const uint32_t*)(ap + g*STR + 2*tg + 8);
                    a[mt][3] = *(const uint32_t*)(ap + (g+8)*STR + 2*tg + 8);
                }
#pragma unroll
                for (int nt = 0; nt < 4; nt++) {
                    uint32_t b[2];
                    const __nv_bfloat16* bp = Bb + (cw*32 + nt*8 + g)*STR + ks*16 + 2*tg;
                    b[0] = *(const uint32_t*)(bp);
                    b[1] = *(const uint32_t*)(bp + 8);
                    mma_bf16(d[0][nt], a[0], b);
                    mma_bf16(d[1][nt], a[1], b);
                }
            }
        }
#pragma unroll
        for (int nt = 0; nt < 4; nt++) {
            const int ch0 = cw*32 + nt*8 + 2*tg;
            const float bv0 = sb[ch0], bv1 = sb[ch0 + 1];
#pragma unroll
            for (int mt = 0; mt < 2; mt++) {
                float v0 = d[mt][nt][0] + bv0, v1 = d[mt][nt][1] + bv1;
                float v2 = d[mt][nt][2] + bv0, v3 = d[mt][nt][3] + bv1;
                const size_t r = (size_t)(row0 + wr0 + mt*16 + g);
                *(float2*)(g_y2 + r*64 + ch0)     = make_float2(v0, v1);
                *(float2*)(g_y2 + (r+8)*64 + ch0) = make_float2(v2, v3);
                ls0[nt] += v0 + v2; ls1[nt] += v1 + v3;
                lq0[nt] += v0*v0 + v2*v2; lq1[nt] += v1*v1 + v3*v3;
            }
        }
    }
#pragma unroll
    for (int nt = 0; nt < 4; nt++) {
        float s0 = ls0[nt], s1 = ls1[nt], q0 = lq0[nt], q1 = lq1[nt];
#pragma unroll
        for (int off = 16; off >= 4; off >>= 1) {
            s0 += __shfl_down_sync(0xffffffffu, s0, off);
            s1 += __shfl_down_sync(0xffffffffu, s1, off);
            q0 += __shfl_down_sync(0xffffffffu, q0, off);
            q1 += __shfl_down_sync(0xffffffffu, q1, off);
        }
        if (g == 0) {
            const int ch0 = cw*32 + nt*8 + 2*tg;
            atomicAdd(&s_sum[ch0],     s0);
            atomicAdd(&s_sum[ch0 + 1], s1);
            atomicAdd(&s_sq [ch0],     q0);
            atomicAdd(&s_sq [ch0 + 1], q1);
        }
    }
    __syncthreads();
    if (tid < 64) {
        atomicAdd(&g_sum2[tid], (double)s_sum[tid]);
        atomicAdd(&g_sq2[tid],  (double)s_sq[tid]);
    }
}

// ---------------- layer 3: mma, 256 threads, 2 blocks/SM (R12) ---------------
__global__ __launch_bounds__(256, 2) void k_layer3m(const float* __restrict__ w,
                                                    const float* __restrict__ bias) {
    extern __shared__ __align__(16) __nv_bfloat16 dsm3[];
    __nv_bfloat16* Ah = dsm3;
    __nv_bfloat16* Al = Ah + 128*STR;
    __nv_bfloat16* Bh = Al + 128*STR;
    __nv_bfloat16* Bl = Bh + 128*STR;
    __shared__ float sa[64], sc[64], sb[128];
    __shared__ float s_sum[128], s_sq[128];
    const int tid = threadIdx.x, wid = tid >> 5, lane = tid & 31;
    const int g = lane >> 2, tg = lane & 3;
    const int rw = wid >> 1, cw = wid & 1;
    const int wr0 = rw * 32;
    if (tid < 64)  { sa[tid]=g_a2[tid]; sc[tid]=g_c2[tid]; }
    if (tid < 128) { sb[tid]=bias[tid]; s_sum[tid]=0.f; s_sq[tid]=0.f; }
    for (int e = tid; e < 8192; e += 256) {
        int n = e >> 6, k = e & 63;
        float v = w[e];
        __nv_bfloat16 h = __float2bfloat16_rn(v);
        __nv_bfloat16 l = __float2bfloat16_rn(v - __bfloat162float(h));
        Bh[n*STR + k] = h; Bl[n*STR + k] = l;
    }
    float ls0[2][4]={{0,0,0,0},{0,0,0,0}}, ls1[2][4]={{0,0,0,0},{0,0,0,0}};
    float lq0[2][4]={{0,0,0,0},{0,0,0,0}}, lq1[2][4]={{0,0,0,0},{0,0,0,0}};
    for (int t = 0; t < 4; t++) {
        const int row0 = (blockIdx.x*4 + t) * 128;
        const int grp = (row0 >> 5) + rw;
        __syncthreads();
        {   // prologue: 2 threads per row
            const int r = tid >> 1, h = tid & 1;
            const float4* yr = (const float4*)(g_y2 + (size_t)(row0 + r)*64);
#pragma unroll
            for (int k8 = 0; k8 < 4; k8++) {
                const int kk = h*4 + k8;
                float x[8]; uint4 H, L;
                bnrelu8(yr[2*kk], yr[2*kk+1], sa, sc, kk, x);
                split8(x, H, L);
                *(uint4*)(Ah + r*STR + kk*8) = H;
                *(uint4*)(Al + r*STR + kk*8) = L;
            }
        }
        __syncthreads();
#pragma unroll
        for (int nh = 0; nh < 2; nh++) {
            float d[2][4][4];
#pragma unroll
            for (int mt = 0; mt < 2; mt++)
#pragma unroll
                for (int nt = 0; nt < 4; nt++)
#pragma unroll
                    for (int q = 0; q < 4; q++) d[mt][nt][q] = 0.f;
#pragma unroll
            for (int pass = 0; pass < 3; pass++) {
                const __nv_bfloat16* Ab = (pass == 2) ? Al : Ah;
                const __nv_bfloat16* Bb = (pass == 1) ? Bl : Bh;
#pragma unroll
                for (int ks = 0; ks < 4; ks++) {
                    uint32_t a[2][4];
#pragma unroll
                    for (int mt = 0; mt < 2; mt++) {
                        const __nv_bfloat16* ap = Ab + (wr0 + mt*16)*STR + ks*16;
                        a[mt][0] = *(const uint32_t*)(ap + g*STR + 2*tg);
                        a[mt][1] = *(const uint32_t*)(ap + (g+8)*STR + 2*tg);
                        a[mt][2] = *(const uint32_t*)(ap + g*STR + 2*tg + 8);
                        a[mt][3] = *(const uint32_t*)(ap + (g+8)*STR + 2*tg + 8);
                    }
#pragma unroll
                    for (int nt = 0; nt < 4; nt++) {
                        uint32_t b[2];
                        const __nv_bfloat16* bp = Bb + (nh*64 + cw*32 + nt*8 + g)*STR + ks*16 + 2*tg;
                        b[0] = *(const uint32_t*)(bp);
                        b[1] = *(const uint32_t*)(bp + 8);
                        mma_bf16(d[0][nt], a[0], b);
                        mma_bf16(d[1][nt], a[1], b);
                    }
                }
            }
#pragma unroll
            for (int nt = 0; nt < 4; nt++) {
                const int ch0 = nh*64 + cw*32 + nt*8 + 2*tg;
                const float bv0 = sb[ch0], bv1 = sb[ch0 + 1];
                float v00 = d[0][nt][0]+bv0, v01 = d[0][nt][1]+bv1;
                float v02 = d[0][nt][2]+bv0, v03 = d[0][nt][3]+bv1;
                float v10 = d[1][nt][0]+bv0, v11 = d[1][nt][1]+bv1;
                float v12 = d[1][nt][2]+bv0, v13 = d[1][nt][3]+bv1;
                ls0[nh][nt] += v00+v02+v10+v12;
                ls1[nh][nt] += v01+v03+v11+v13;
                lq0[nh][nt] += v00*v00+v02*v02+v10*v10+v12*v12;
                lq1[nh][nt] += v01*v01+v03*v03+v11*v11+v13*v13;
                float mx0 = fmaxf(fmaxf(v00,v02), fmaxf(v10,v12));
                float mx1 = fmaxf(fmaxf(v01,v03), fmaxf(v11,v13));
                float mn0 = fminf(fminf(v00,v02), fminf(v10,v12));
                float mn1 = fminf(fminf(v01,v03), fminf(v11,v13));
#pragma unroll
                for (int off = 16; off >= 4; off >>= 1) {
                    mx0 = fmaxf(mx0, __shfl_down_sync(0xffffffffu, mx0, off));
                    mx1 = fmaxf(mx1, __shfl_down_sync(0xffffffffu, mx1, off));
                    mn0 = fminf(mn0, __shfl_down_sync(0xffffffffu, mn0, off));
                    mn1 = fminf(mn1, __shfl_down_sync(0xffffffffu, mn1, off));
                }
                if (g == 0) {
                    g_mx[(size_t)grp*128 + ch0]     = mx0;
                    g_mx[(size_t)grp*128 + ch0 + 1] = mx1;
                    g_mn[(size_t)grp*128 + ch0]     = mn0;
                    g_mn[(size_t)grp*128 + ch0 + 1] = mn1;
                }
            }
        }
    }
#pragma unroll
    for (int nh = 0; nh < 2; nh++)
#pragma unroll
    for (int nt = 0; nt < 4; nt++) {
        float s0 = ls0[nh][nt], s1 = ls1[nh][nt];
        float q0 = lq0[nh][nt], q1 = lq1[nh][nt];
#pragma unroll
        for (int off = 16; off >= 4; off >>= 1) {
            s0 += __shfl_down_sync(0xffffffffu, s0, off);
            s1 += __shfl_down_sync(0xffffffffu, s1, off);
            q0 += __shfl_down_sync(0xffffffffu, q0, off);
            q1 += __shfl_down_sync(0xffffffffu, q1, off);
        }
        if (g == 0) {
            const int ch0 = nh*64 + cw*32 + nt*8 + 2*tg;
            atomicAdd(&s_sum[ch0],     s0);
            atomicAdd(&s_sum[ch0 + 1], s1);
            atomicAdd(&s_sq [ch0],     q0);
            atomicAdd(&s_sq [ch0 + 1], q1);
        }
    }
    __syncthreads();
    if (tid < 128) {
        atomicAdd(&g_sum3[tid], (double)s_sum[tid]);
        atomicAdd(&g_sq3[tid],  (double)s_sq[tid]);
    }
}

// ---------------- BN parameter derivation ------------------------------------
__global__ void k_bn(int layer, const float* __restrict__ gg,
                     const float* __restrict__ be, int n) {
    int i = threadIdx.x;
    if (i >= n) return;
    const double* sum; const double* sq; float* a; float* c;
    if (layer == 0)      { sum = g_sum1; sq = g_sq1; a = g_a1; c = g_c1; }
    else if (layer == 1) { sum = g_sum2; sq = g_sq2; a = g_a2; c = g_c2; }
    else                 { sum = g_sum3; sq = g_sq3; a = g_a3; c = g_c3; }
    const double invM = 1.0 / (double)M_ROWS;
    double mean = sum[i] * invM;
    double var  = sq[i] * invM - mean * mean;
    double A = (double)gg[i] / sqrt(var + 1e-5);
    a[i] = (float)A;
    c[i] = (float)((double)be[i] - A * mean);
}

// ---------------- final ------------------------------------------------------
__global__ __launch_bounds__(256) void k_final(float* __restrict__ out) {
    int gid = blockIdx.x * 256 + threadIdx.x;
    int s  = gid & 1023;
    int ch = (gid >> 10) & 127;
    int b  = gid >> 17;
    float A = g_a3[ch], C = g_c3[ch];
    size_t gi = ((size_t)((b << 10) | s))*128 + ch;
    float m = (A >= 0.f) ? g_mx[gi] : g_mn[gi];
    out[OUT_XYZ_ELEMS + gid] = fmaxf(fmaf(A, m, C), 0.f);
}

// ---------------- launch -----------------------------------------------------
extern "C" void kernel_launch(void* const* d_in, const int* in_sizes, int n_in,
                              void* d_out, int out_size) {
    const float* xyz    = (const float*)d_in[0];
    const float* points = (const float*)d_in[1];
    const float* w0  = (const float*)d_in[2];
    const float* b0  = (const float*)d_in[3];
    const float* g0  = (const float*)d_in[4];
    const float* be0 = (const float*)d_in[5];
    const float* w1  = (const float*)d_in[6];
    const float* b1  = (const float*)d_in[7];
    const float* g1  = (const float*)d_in[8];
    const float* be1 = (const float*)d_in[9];
    const float* w2  = (const float*)d_in[10];
    const float* b2  = (const float*)d_in[11];
    const float* g2  = (const float*)d_in[12];
    const float* be2 = (const float*)d_in[13];
    float* out = (float*)d_out;
    (void)in_sizes; (void)n_in; (void)out_size;

    const size_t smem_xyz  = (size_t)3 * NN * sizeof(float);      // 48KB
    const size_t smem_l2   = (size_t)(2*128*STR + 2*64*STR) * 2;  // 55296B
    const size_t smem_l3   = (size_t)(2*128*STR + 2*128*STR) * 2; // 73728B
    static int attr_done = 0;
    if (!attr_done) {
        cudaFuncSetAttribute(k_fps,  cudaFuncAttributeMaxDynamicSharedMemorySize, (int)smem_xyz);
        cudaFuncSetAttribute(k_ball, cudaFuncAttributeMaxDynamicSharedMemorySize, (int)smem_xyz);
        cudaFuncSetAttribute(k_layer2m, cudaFuncAttributeMaxDynamicSharedMemorySize, (int)smem_l2);
        cudaFuncSetAttribute(k_layer3m, cudaFuncAttributeMaxDynamicSharedMemorySize, (int)smem_l3);
        attr_done = 1;
    }

    k_init<<<1, 128>>>();
    k_fps<<<BB, 512, smem_xyz>>>(xyz, out);
    k_ball<<<dim3(SS/32, BB), 1024, smem_xyz>>>(xyz, out);
    k_layer1<<<1024, 256>>>(xyz, points, out, w0, b0);
    k_bn<<<1, 128>>>(0, g0, be0, 64);
    k_layer2m<<<1024, 256, smem_l2>>>(w1, b1);
    k_bn<<<1, 128>>>(1, g1, be1, 64);
    k_layer3m<<<1024, 256, smem_l3>>>(w2, b2);
    k_bn<<<1, 128>>>(2, g2, be2, 128);
    k_final<<<(BB*128*SS)/256, 256>>>(out);
}